// round 12
// baseline (speedup 1.0000x reference)
#include <cuda_runtime.h>
#include <cstdint>

// PadVariable reflect-pad gather — FINAL.
// out[n,t,:] = x[n, reflect(t - pad0[n], lens[n]), :], zero where t >= L+p0+p1.
//
// Converged after 11 rounds: the kernel runs at ~93-96% of the compulsory-
// traffic DRAM floor (~150MB/replay). Config = measured best across 8
// structural variants: blockIdx.y = n, blockIdx.x = tile of TILE_T=64 t's,
// 256 threads (f4 = tid & 15, trow = tid >> 4), UNROLL=4, 32-bit indexing,
// front-batched loads (MLP=4), __stcs evict-first streaming stores.
// This round adds a fast unpredicated path for interior (full) tiles; only
// the last tile per row takes the bounds-checked path.

#define F4_      16   // F=64 floats -> 16 float4
#define TROWS_   16   // 256 / F4_
#define UNROLL_  4
#define TILE_T_  (TROWS_ * UNROLL_)   // 64 t per block

__global__ __launch_bounds__(256)
void pad_variable_kernel(const float4* __restrict__ x4,
                         const int* __restrict__ lens,
                         const int* __restrict__ pad,  // (2, N)
                         float4* __restrict__ out4,
                         int N, int T, int Tp) {
    const int n     = blockIdx.y;
    const int tid   = threadIdx.x;
    const int f4    = tid & (F4_ - 1);
    const int trow  = tid >> 4;
    const int tbase = blockIdx.x * TILE_T_;
    const int t0    = tbase + trow;

    const int L  = __ldg(&lens[n]);
    const int p0 = __ldg(&pad[n]);
    const int p1 = __ldg(&pad[N + n]);
    const int vlim = L + p0 + p1;

    // 32-bit element offsets (max ~6.3M float4 < 2^31 bytes) — safe here.
    const float4* __restrict__ xrow = x4 + (unsigned)(n * T * F4_);
    float4* __restrict__ orow       = out4 + (unsigned)(n * Tp * F4_);

    int t[UNROLL_];
    int idx[UNROLL_];
    bool load_ok[UNROLL_];

    #pragma unroll
    for (int u = 0; u < UNROLL_; u++) {
        t[u] = t0 + u * TROWS_;
        int rel = t[u] - p0;
        int s = (rel < 0) ? -rel : ((rel < L) ? rel : (2 * L - rel - 2));
        s = min(max(s, 0), T - 1);
        idx[u] = s * F4_ + f4;
        load_ok[u] = t[u] < vlim;
    }

    float4 v[UNROLL_];

    if (tbase + TILE_T_ <= Tp) {
        // Fast path: full tile, no store bounds checks.
        #pragma unroll
        for (int u = 0; u < UNROLL_; u++) {
            if (load_ok[u])
                v[u] = __ldg(&xrow[(unsigned)idx[u]]);
            else
                v[u] = make_float4(0.f, 0.f, 0.f, 0.f);
        }
        #pragma unroll
        for (int u = 0; u < UNROLL_; u++)
            __stcs(&orow[(unsigned)(t[u] * F4_ + f4)], v[u]);
    } else {
        // Tail tile: bounds-checked.
        #pragma unroll
        for (int u = 0; u < UNROLL_; u++) {
            if (load_ok[u] && t[u] < Tp)
                v[u] = __ldg(&xrow[(unsigned)idx[u]]);
            else
                v[u] = make_float4(0.f, 0.f, 0.f, 0.f);
        }
        #pragma unroll
        for (int u = 0; u < UNROLL_; u++) {
            if (t[u] < Tp)
                __stcs(&orow[(unsigned)(t[u] * F4_ + f4)], v[u]);
        }
    }
}

extern "C" void kernel_launch(void* const* d_in, const int* in_sizes, int n_in,
                              void* d_out, int out_size) {
    const float* x    = (const float*)d_in[0];  // (N, T, F) float32
    const int*   lens = (const int*)d_in[1];    // (N,)
    const int*   pad  = (const int*)d_in[2];    // (2, N)

    float* out = (float*)d_out;

    const int N = in_sizes[1];           // 64
    const int F = 64;                    // feature dim (16 float4)
    const int T = in_sizes[0] / (N * F); // 4096
    const int Tp = out_size / (N * F);

    dim3 grid((Tp + TILE_T_ - 1) / TILE_T_, N);
    pad_variable_kernel<<<grid, 256>>>(
        (const float4*)x, lens, pad, (float4*)out, N, T, Tp);
}

// round 13
// speedup vs baseline: 1.0638x; 1.0638x over previous
#include <cuda_runtime.h>
#include <cstdint>

// PadVariable reflect-pad gather — FINAL (converged, R12 config).
// out[n,t,:] = x[n, reflect(t - pad0[n], lens[n]), :], zero where t >= L+p0+p1.
//
// Converged after 12 rounds at ~90% of the compulsory-traffic DRAM floor
// (~150MB/replay, ~7.2TB/s effective vs 8TB/s spec). Measured-best config:
// blockIdx.y = n, blockIdx.x = tile of TILE_T=64 t's, 256 threads
// (f4 = tid & 15, trow = tid >> 4), UNROLL=4, 32-bit indexing, front-batched
// loads (MLP=4), __stcs evict-first streaming stores, unpredicated fast path
// for interior tiles. Tested-and-rejected: MLP=8, persistent grid,
// cp.async.bulk stores, L2 evict_last, 256-bit ld/st, 512-thread blocks.

#define F4_      16   // F=64 floats -> 16 float4
#define TROWS_   16   // 256 / F4_
#define UNROLL_  4
#define TILE_T_  (TROWS_ * UNROLL_)   // 64 t per block

__global__ __launch_bounds__(256)
void pad_variable_kernel(const float4* __restrict__ x4,
                         const int* __restrict__ lens,
                         const int* __restrict__ pad,  // (2, N)
                         float4* __restrict__ out4,
                         int N, int T, int Tp) {
    const int n     = blockIdx.y;
    const int tid   = threadIdx.x;
    const int f4    = tid & (F4_ - 1);
    const int trow  = tid >> 4;
    const int tbase = blockIdx.x * TILE_T_;
    const int t0    = tbase + trow;

    const int L  = __ldg(&lens[n]);
    const int p0 = __ldg(&pad[n]);
    const int p1 = __ldg(&pad[N + n]);
    const int vlim = L + p0 + p1;

    // 32-bit element offsets (max ~6.3M float4 < 2^31 bytes) — safe here.
    const float4* __restrict__ xrow = x4 + (unsigned)(n * T * F4_);
    float4* __restrict__ orow       = out4 + (unsigned)(n * Tp * F4_);

    int t[UNROLL_];
    int idx[UNROLL_];
    bool load_ok[UNROLL_];

    #pragma unroll
    for (int u = 0; u < UNROLL_; u++) {
        t[u] = t0 + u * TROWS_;
        int rel = t[u] - p0;
        int s = (rel < 0) ? -rel : ((rel < L) ? rel : (2 * L - rel - 2));
        s = min(max(s, 0), T - 1);
        idx[u] = s * F4_ + f4;
        load_ok[u] = t[u] < vlim;
    }

    float4 v[UNROLL_];

    if (tbase + TILE_T_ <= Tp) {
        // Fast path: full tile, no store bounds checks.
        #pragma unroll
        for (int u = 0; u < UNROLL_; u++) {
            if (load_ok[u])
                v[u] = __ldg(&xrow[(unsigned)idx[u]]);
            else
                v[u] = make_float4(0.f, 0.f, 0.f, 0.f);
        }
        #pragma unroll
        for (int u = 0; u < UNROLL_; u++)
            __stcs(&orow[(unsigned)(t[u] * F4_ + f4)], v[u]);
    } else {
        // Tail tile: bounds-checked.
        #pragma unroll
        for (int u = 0; u < UNROLL_; u++) {
            if (load_ok[u] && t[u] < Tp)
                v[u] = __ldg(&xrow[(unsigned)idx[u]]);
            else
                v[u] = make_float4(0.f, 0.f, 0.f, 0.f);
        }
        #pragma unroll
        for (int u = 0; u < UNROLL_; u++) {
            if (t[u] < Tp)
                __stcs(&orow[(unsigned)(t[u] * F4_ + f4)], v[u]);
        }
    }
}

extern "C" void kernel_launch(void* const* d_in, const int* in_sizes, int n_in,
                              void* d_out, int out_size) {
    const float* x    = (const float*)d_in[0];  // (N, T, F) float32
    const int*   lens = (const int*)d_in[1];    // (N,)
    const int*   pad  = (const int*)d_in[2];    // (2, N)

    float* out = (float*)d_out;

    const int N = in_sizes[1];           // 64
    const int F = 64;                    // feature dim (16 float4)
    const int T = in_sizes[0] / (N * F); // 4096
    const int Tp = out_size / (N * F);

    dim3 grid((Tp + TILE_T_ - 1) / TILE_T_, N);
    pad_variable_kernel<<<grid, 256>>>(
        (const float4*)x, lens, pad, (float4*)out, N, T, Tp);
}